// round 8
// baseline (speedup 1.0000x reference)
#include <cuda_runtime.h>

// Problem constants
#define BB     4
#define QL     512
#define KVL    2048
#define PASTL  1536           // KVL - QL
#define NQO    32
#define NKV    8
#define GQ     4              // GQA group size
#define HEADD  128
#define NT     64             // kv tile size
#define MROWS  128            // rows per CTA = 32 q positions x 4 grouped heads

// smem strides (padded for conflict-free access)
#define QSS 129
#define KSS 65
#define PSS 129

// smem layout offsets (floats)
#define QS_OFF 0                         // 128*129 = 16512
#define KS_OFF 16512                     // 128*65  = 8320
#define VS_OFF 24832                     // 64*128  = 8192
#define PS_OFF 33024                     // 64*129  = 8256
#define MS_OFF 41280
#define LS_OFF 41408
#define AS_OFF 41536
#define SMEM_FLOATS 41664                // 166656 bytes

// gathered contiguous K/V: [b][h][t][d]
__device__ float g_K[BB * NKV * KVL * HEADD];
__device__ float g_V[BB * NKV * KVL * HEADD];

__device__ __forceinline__ float ex2f(float x) {
    float r;
    asm("ex2.approx.ftz.f32 %0, %1;" : "=f"(r) : "f"(x));
    return r;
}

// Phase 1: resolve paged indirection once.
// For t < PASTL read the cache via block_tables; for t >= PASTL the reference
// scatters key/value into exactly those slots, so read key/value directly.
__global__ void gather_kv_kernel(const float* __restrict__ key,
                                 const float* __restrict__ value,
                                 const float* __restrict__ kcache,
                                 const float* __restrict__ vcache,
                                 const int*   __restrict__ bt)
{
    int idx = blockIdx.x * blockDim.x + threadIdx.x;   // float4 index
    if (idx >= BB * NKV * KVL * (HEADD / 4)) return;
    // idx bits: [4:0]=d4, [15:5]=t, [18:16]=h, [20:19]=b ; dst float4 index == idx
    int d4 = idx & 31;
    int t  = (idx >> 5) & (KVL - 1);
    int h  = (idx >> 16) & (NKV - 1);
    int b  = idx >> 19;
    float4 kv, vv;
    if (t < PASTL) {
        int blk  = bt[b * (KVL / 16) + (t >> 4)];
        int slot = blk * 16 + (t & 15);
        size_t off = ((size_t)slot * NKV + h) * 32 + d4;
        kv = ((const float4*)kcache)[off];
        vv = ((const float4*)vcache)[off];
    } else {
        size_t tok = (size_t)b * QL + (t - PASTL);
        size_t off = tok * (NKV * HEADD / 4) + (size_t)h * 32 + d4;
        kv = ((const float4*)key)[off];
        vv = ((const float4*)value)[off];
    }
    ((float4*)g_K)[idx] = kv;
    ((float4*)g_V)[idx] = vv;
}

// Phase 2: flash attention.
// grid.x = b*NKV (32), grid.y = q tile (16 tiles of 32 q positions)
// CTA rows: r = j*32 + qq  (j = grouped query head 0..3, qq = q within tile)
__global__ __launch_bounds__(256, 1)
void attn_kernel(const float* __restrict__ query, float* __restrict__ out)
{
    extern __shared__ float sm[];
    float* Qs = sm + QS_OFF;   // [kk][row] stride QSS
    float* Ks = sm + KS_OFF;   // [kk][c]   stride KSS
    float* Vs = sm + VS_OFF;   // [c][d]    stride 128
    float* Ps = sm + PS_OFF;   // [c][row]  stride PSS
    float* Ms = sm + MS_OFF;
    float* Ls = sm + LS_OFF;
    float* As = sm + AS_OFF;

    const int tid = threadIdx.x;
    const int b   = blockIdx.x >> 3;
    const int h   = blockIdx.x & 7;
    const int q0  = blockIdx.y << 5;

    // log2(e)/sqrt(128): fold softmax scale + base-2 conversion into Q
    const float SCALE = 0.12751740f;

    // ---- load Q tile (128 rows x 128 dims), scaled, transposed to [kk][row]
    for (int idx = tid; idx < MROWS * HEADD; idx += 256) {
        int r  = idx >> 7;           // row
        int kk = idx & 127;          // head dim
        int j  = r >> 5;
        int qq = r & 31;
        float v = query[((size_t)(b * QL + q0 + qq)) * (NQO * HEADD)
                        + (h * GQ + j) * HEADD + kk];
        Qs[kk * QSS + r] = v * SCALE;
    }
    if (tid < MROWS) { Ms[tid] = -1e30f; Ls[tid] = 0.0f; }
    __syncthreads();

    const int ty = tid >> 4;     // 0..15
    const int tx = tid & 15;     // 0..15

    float acc[8][8];
#pragma unroll
    for (int i = 0; i < 8; i++)
#pragma unroll
        for (int j = 0; j < 8; j++) acc[i][j] = 0.0f;

    const int kv_hi  = PASTL + q0 + 31;        // max kv index any row may see
    const int ntiles = kv_hi / NT + 1;

    const float* Kgp = g_K + ((size_t)(b * NKV + h)) * KVL * HEADD;
    const float* Vgp = g_V + ((size_t)(b * NKV + h)) * KVL * HEADD;

    for (int tile = 0; tile < ntiles; ++tile) {
        const int t0 = tile * NT;

        // ---- load K (transposed [kk][c]) and V ([c][d]) tiles
        for (int idx = tid; idx < NT * HEADD; idx += 256) {
            int c  = idx >> 7;
            int kk = idx & 127;
            Ks[kk * KSS + c] = Kgp[(size_t)(t0 + c) * HEADD + kk];
        }
        for (int idx4 = tid; idx4 < NT * (HEADD / 4); idx4 += 256) {
            int c  = idx4 >> 5;
            int d4 = idx4 & 31;
            ((float4*)Vs)[c * 32 + d4] =
                ((const float4*)Vgp)[(size_t)(t0 + c) * 32 + d4];
        }
        __syncthreads();

        // ---- S = Q K^T  (per-thread 8 rows x 4 cols)
        float s[8][4];
#pragma unroll
        for (int i = 0; i < 8; i++)
#pragma unroll
            for (int j = 0; j < 4; j++) s[i][j] = 0.0f;

#pragma unroll 2
        for (int kk = 0; kk < HEADD; ++kk) {
            float qv[8], kvv[4];
#pragma unroll
            for (int i = 0; i < 8; i++) qv[i] = Qs[kk * QSS + ty + 16 * i];
#pragma unroll
            for (int j = 0; j < 4; j++) kvv[j] = Ks[kk * KSS + tx + 16 * j];
#pragma unroll
            for (int i = 0; i < 8; i++)
#pragma unroll
                for (int j = 0; j < 4; j++) s[i][j] = fmaf(qv[i], kvv[j], s[i][j]);
        }

        // ---- causal mask + write S to smem as [c][row]
#pragma unroll
        for (int i = 0; i < 8; i++) {
            int r   = ty + 16 * i;
            int lim = PASTL + q0 + (r & 31);   // max allowed kv index
#pragma unroll
            for (int j = 0; j < 4; j++) {
                int c = tx + 16 * j;
                Ps[c * PSS + r] = ((t0 + c) > lim) ? -1e30f : s[i][j];
            }
        }
        __syncthreads();

        // ---- online softmax, one thread per row
        if (tid < MROWS) {
            int r = tid;
            float mt = -1e30f;
#pragma unroll 4
            for (int c = 0; c < NT; ++c) mt = fmaxf(mt, Ps[c * PSS + r]);
            float mo = Ms[r];
            float mn = fmaxf(mo, mt);
            float al = ex2f(mo - mn);
            float sum = 0.0f;
#pragma unroll 4
            for (int c = 0; c < NT; ++c) {
                float p = ex2f(Ps[c * PSS + r] - mn);
                Ps[c * PSS + r] = p;
                sum += p;
            }
            Ls[r] = Ls[r] * al + sum;
            Ms[r] = mn;
            As[r] = al;
        }
        __syncthreads();

        // ---- rescale O, then O += P V  (per-thread 8x8)
        float al[8];
#pragma unroll
        for (int i = 0; i < 8; i++) al[i] = As[ty + 16 * i];
#pragma unroll
        for (int i = 0; i < 8; i++)
#pragma unroll
            for (int j = 0; j < 8; j++) acc[i][j] *= al[i];

#pragma unroll 2
        for (int c = 0; c < NT; ++c) {
            float pv[8], vv[8];
#pragma unroll
            for (int i = 0; i < 8; i++) pv[i] = Ps[c * PSS + ty + 16 * i];
#pragma unroll
            for (int j = 0; j < 8; j++) vv[j] = Vs[c * HEADD + tx + 16 * j];
#pragma unroll
            for (int i = 0; i < 8; i++)
#pragma unroll
                for (int j = 0; j < 8; j++)
                    acc[i][j] = fmaf(pv[i], vv[j], acc[i][j]);
        }
        __syncthreads();   // before next tile overwrites Ks/Vs/Ps
    }

    // ---- epilogue: divide by l, write out
    float il[8];
#pragma unroll
    for (int i = 0; i < 8; i++) il[i] = 1.0f / Ls[ty + 16 * i];
#pragma unroll
    for (int i = 0; i < 8; i++) {
        int r  = ty + 16 * i;
        int jh = r >> 5;
        int qq = r & 31;
        float* orow = out + ((size_t)(b * QL + q0 + qq)) * (NQO * HEADD)
                          + (h * GQ + jh) * HEADD;
#pragma unroll
        for (int j = 0; j < 8; j++) orow[tx + 16 * j] = acc[i][j] * il[i];
    }
}

extern "C" void kernel_launch(void* const* d_in, const int* in_sizes, int n_in,
                              void* d_out, int out_size)
{
    const float* query  = (const float*)d_in[0];
    const float* key    = (const float*)d_in[1];
    const float* value  = (const float*)d_in[2];
    const float* kcache = (const float*)d_in[3];
    const float* vcache = (const float*)d_in[4];
    const int*   bt     = (const int*)d_in[5];
    // d_in[6] = new_cache_slots (unused: slots are derivable from block_tables)
    float* out = (float*)d_out;

    // Phase 1: gather paged KV into contiguous scratch
    int total4 = BB * NKV * KVL * (HEADD / 4);
    gather_kv_kernel<<<(total4 + 255) / 256, 256>>>(key, value, kcache, vcache, bt);

    // Phase 2: flash attention
    cudaFuncSetAttribute(attn_kernel, cudaFuncAttributeMaxDynamicSharedMemorySize,
                         SMEM_FLOATS * 4);
    dim3 grid(BB * NKV, QL / 32);
    attn_kernel<<<grid, 256, SMEM_FLOATS * 4>>>(query, out);
}

// round 9
// speedup vs baseline: 1.0025x; 1.0025x over previous
#include <cuda_runtime.h>

// Problem constants
#define BB     4
#define QL     512
#define KVL    2048
#define PASTL  1536           // KVL - QL
#define NQO    32
#define NKV    8
#define GQ     4              // GQA group size
#define HEADD  128
#define NT     64             // kv tile size
#define MROWS  128            // rows per CTA = 32 q positions x 4 grouped heads

// smem strides (padded for conflict-free access)
#define QSS 129
#define KSS 65
#define PSS 129

// smem layout offsets (floats)
#define QS_OFF 0                         // 128*129 = 16512
#define KS_OFF 16512                     // 128*65  = 8320
#define VS_OFF 24832                     // 64*128  = 8192
#define PS_OFF 33024                     // 64*129  = 8256
#define MS_OFF 41280
#define LS_OFF 41408
#define AS_OFF 41536
#define SMEM_FLOATS 41664                // 166656 bytes

// gathered contiguous K/V: [b][h][t][d]
__device__ float g_K[BB * NKV * KVL * HEADD];
__device__ float g_V[BB * NKV * KVL * HEADD];

__device__ __forceinline__ float ex2f(float x) {
    float r;
    asm("ex2.approx.ftz.f32 %0, %1;" : "=f"(r) : "f"(x));
    return r;
}

// Phase 1: resolve paged indirection once.
// For t < PASTL read the cache via block_tables; for t >= PASTL the reference
// scatters key/value into exactly those slots, so read key/value directly.
__global__ void gather_kv_kernel(const float* __restrict__ key,
                                 const float* __restrict__ value,
                                 const float* __restrict__ kcache,
                                 const float* __restrict__ vcache,
                                 const int*   __restrict__ bt)
{
    int idx = blockIdx.x * blockDim.x + threadIdx.x;   // float4 index
    if (idx >= BB * NKV * KVL * (HEADD / 4)) return;
    // idx bits: [4:0]=d4, [15:5]=t, [18:16]=h, [20:19]=b ; dst float4 index == idx
    int d4 = idx & 31;
    int t  = (idx >> 5) & (KVL - 1);
    int h  = (idx >> 16) & (NKV - 1);
    int b  = idx >> 19;
    float4 kv, vv;
    if (t < PASTL) {
        int blk  = bt[b * (KVL / 16) + (t >> 4)];
        int slot = blk * 16 + (t & 15);
        size_t off = ((size_t)slot * NKV + h) * 32 + d4;
        kv = ((const float4*)kcache)[off];
        vv = ((const float4*)vcache)[off];
    } else {
        size_t tok = (size_t)b * QL + (t - PASTL);
        size_t off = tok * (NKV * HEADD / 4) + (size_t)h * 32 + d4;
        kv = ((const float4*)key)[off];
        vv = ((const float4*)value)[off];
    }
    ((float4*)g_K)[idx] = kv;
    ((float4*)g_V)[idx] = vv;
}

// Phase 2: flash attention.
// grid.x = b*NKV (32), grid.y = q tile (16 tiles of 32 q positions)
// CTA rows: r = j*32 + qq  (j = grouped query head 0..3, qq = q within tile)
__global__ __launch_bounds__(256, 1)
void attn_kernel(const float* __restrict__ query, float* __restrict__ out)
{
    extern __shared__ float sm[];
    float* Qs = sm + QS_OFF;   // [kk][row] stride QSS
    float* Ks = sm + KS_OFF;   // [kk][c]   stride KSS
    float* Vs = sm + VS_OFF;   // [c][d]    stride 128
    float* Ps = sm + PS_OFF;   // [c][row]  stride PSS
    float* Ms = sm + MS_OFF;
    float* Ls = sm + LS_OFF;
    float* As = sm + AS_OFF;

    const int tid = threadIdx.x;
    const int b   = blockIdx.x >> 3;
    const int h   = blockIdx.x & 7;
    const int q0  = blockIdx.y << 5;

    // log2(e)/sqrt(128): fold softmax scale + base-2 conversion into Q
    const float SCALE = 0.12751740f;

    // ---- load Q tile (128 rows x 128 dims), scaled, transposed to [kk][row]
    for (int idx = tid; idx < MROWS * HEADD; idx += 256) {
        int r  = idx >> 7;           // row
        int kk = idx & 127;          // head dim
        int j  = r >> 5;
        int qq = r & 31;
        float v = query[((size_t)(b * QL + q0 + qq)) * (NQO * HEADD)
                        + (h * GQ + j) * HEADD + kk];
        Qs[kk * QSS + r] = v * SCALE;
    }
    if (tid < MROWS) { Ms[tid] = -1e30f; Ls[tid] = 0.0f; }
    __syncthreads();

    const int ty = tid >> 4;     // 0..15
    const int tx = tid & 15;     // 0..15

    float acc[8][8];
#pragma unroll
    for (int i = 0; i < 8; i++)
#pragma unroll
        for (int j = 0; j < 8; j++) acc[i][j] = 0.0f;

    const int kv_hi  = PASTL + q0 + 31;        // max kv index any row may see
    const int ntiles = kv_hi / NT + 1;

    const float* Kgp = g_K + ((size_t)(b * NKV + h)) * KVL * HEADD;
    const float* Vgp = g_V + ((size_t)(b * NKV + h)) * KVL * HEADD;

    for (int tile = 0; tile < ntiles; ++tile) {
        const int t0 = tile * NT;

        // ---- load K (transposed [kk][c]) and V ([c][d]) tiles
        for (int idx = tid; idx < NT * HEADD; idx += 256) {
            int c  = idx >> 7;
            int kk = idx & 127;
            Ks[kk * KSS + c] = Kgp[(size_t)(t0 + c) * HEADD + kk];
        }
        for (int idx4 = tid; idx4 < NT * (HEADD / 4); idx4 += 256) {
            int c  = idx4 >> 5;
            int d4 = idx4 & 31;
            ((float4*)Vs)[c * 32 + d4] =
                ((const float4*)Vgp)[(size_t)(t0 + c) * 32 + d4];
        }
        __syncthreads();

        // ---- S = Q K^T  (per-thread 8 rows x 4 cols)
        float s[8][4];
#pragma unroll
        for (int i = 0; i < 8; i++)
#pragma unroll
            for (int j = 0; j < 4; j++) s[i][j] = 0.0f;

#pragma unroll 2
        for (int kk = 0; kk < HEADD; ++kk) {
            float qv[8], kvv[4];
#pragma unroll
            for (int i = 0; i < 8; i++) qv[i] = Qs[kk * QSS + ty + 16 * i];
#pragma unroll
            for (int j = 0; j < 4; j++) kvv[j] = Ks[kk * KSS + tx + 16 * j];
#pragma unroll
            for (int i = 0; i < 8; i++)
#pragma unroll
                for (int j = 0; j < 4; j++) s[i][j] = fmaf(qv[i], kvv[j], s[i][j]);
        }

        // ---- causal mask + write S to smem as [c][row]
#pragma unroll
        for (int i = 0; i < 8; i++) {
            int r   = ty + 16 * i;
            int lim = PASTL + q0 + (r & 31);   // max allowed kv index
#pragma unroll
            for (int j = 0; j < 4; j++) {
                int c = tx + 16 * j;
                Ps[c * PSS + r] = ((t0 + c) > lim) ? -1e30f : s[i][j];
            }
        }
        __syncthreads();

        // ---- online softmax, one thread per row
        if (tid < MROWS) {
            int r = tid;
            float mt = -1e30f;
#pragma unroll 4
            for (int c = 0; c < NT; ++c) mt = fmaxf(mt, Ps[c * PSS + r]);
            float mo = Ms[r];
            float mn = fmaxf(mo, mt);
            float al = ex2f(mo - mn);
            float sum = 0.0f;
#pragma unroll 4
            for (int c = 0; c < NT; ++c) {
                float p = ex2f(Ps[c * PSS + r] - mn);
                Ps[c * PSS + r] = p;
                sum += p;
            }
            Ls[r] = Ls[r] * al + sum;
            Ms[r] = mn;
            As[r] = al;
        }
        __syncthreads();

        // ---- rescale O, then O += P V  (per-thread 8x8)
        float al[8];
#pragma unroll
        for (int i = 0; i < 8; i++) al[i] = As[ty + 16 * i];
#pragma unroll
        for (int i = 0; i < 8; i++)
#pragma unroll
            for (int j = 0; j < 8; j++) acc[i][j] *= al[i];

#pragma unroll 2
        for (int c = 0; c < NT; ++c) {
            float pv[8], vv[8];
#pragma unroll
            for (int i = 0; i < 8; i++) pv[i] = Ps[c * PSS + ty + 16 * i];
#pragma unroll
            for (int j = 0; j < 8; j++) vv[j] = Vs[c * HEADD + tx + 16 * j];
#pragma unroll
            for (int i = 0; i < 8; i++)
#pragma unroll
                for (int j = 0; j < 8; j++)
                    acc[i][j] = fmaf(pv[i], vv[j], acc[i][j]);
        }
        __syncthreads();   // before next tile overwrites Ks/Vs/Ps
    }

    // ---- epilogue: divide by l, write out
    float il[8];
#pragma unroll
    for (int i = 0; i < 8; i++) il[i] = 1.0f / Ls[ty + 16 * i];
#pragma unroll
    for (int i = 0; i < 8; i++) {
        int r  = ty + 16 * i;
        int jh = r >> 5;
        int qq = r & 31;
        float* orow = out + ((size_t)(b * QL + q0 + qq)) * (NQO * HEADD)
                          + (h * GQ + jh) * HEADD;
#pragma unroll
        for (int j = 0; j < 8; j++) orow[tx + 16 * j] = acc[i][j] * il[i];
    }
}

extern "C" void kernel_launch(void* const* d_in, const int* in_sizes, int n_in,
                              void* d_out, int out_size)
{
    const float* query  = (const float*)d_in[0];
    const float* key    = (const float*)d_in[1];
    const float* value  = (const float*)d_in[2];
    const float* kcache = (const float*)d_in[3];
    const float* vcache = (const float*)d_in[4];
    const int*   bt     = (const int*)d_in[5];
    // d_in[6] = new_cache_slots (unused: slots are derivable from block_tables)
    float* out = (float*)d_out;

    // Phase 1: gather paged KV into contiguous scratch
    int total4 = BB * NKV * KVL * (HEADD / 4);
    gather_kv_kernel<<<(total4 + 255) / 256, 256>>>(key, value, kcache, vcache, bt);

    // Phase 2: flash attention
    cudaFuncSetAttribute(attn_kernel, cudaFuncAttributeMaxDynamicSharedMemorySize,
                         SMEM_FLOATS * 4);
    dim3 grid(BB * NKV, QL / 32);
    attn_kernel<<<grid, 256, SMEM_FLOATS * 4>>>(query, out);
}

// round 10
// speedup vs baseline: 1.0043x; 1.0018x over previous
#include <cuda_runtime.h>

// Problem constants
#define BB     4
#define QL     512
#define KVL    2048
#define PASTL  1536           // KVL - QL
#define NQO    32
#define NKV    8
#define GQ     4              // GQA group size
#define HEADD  128
#define NT     64             // kv tile size
#define MROWS  128            // rows per CTA = 32 q positions x 4 grouped heads

// smem strides (padded for conflict-free access)
#define QSS 129
#define KSS 65
#define PSS 129

// smem layout offsets (floats)
#define QS_OFF 0                         // 128*129 = 16512
#define KS_OFF 16512                     // 128*65  = 8320
#define VS_OFF 24832                     // 64*128  = 8192
#define PS_OFF 33024                     // 64*129  = 8256
#define MS_OFF 41280
#define LS_OFF 41408
#define AS_OFF 41536
#define SMEM_FLOATS 41664                // 166656 bytes

// gathered contiguous K/V: [b][h][t][d]
__device__ float g_K[BB * NKV * KVL * HEADD];
__device__ float g_V[BB * NKV * KVL * HEADD];

__device__ __forceinline__ float ex2f(float x) {
    float r;
    asm("ex2.approx.ftz.f32 %0, %1;" : "=f"(r) : "f"(x));
    return r;
}

// Phase 1: resolve paged indirection once.
// For t < PASTL read the cache via block_tables; for t >= PASTL the reference
// scatters key/value into exactly those slots, so read key/value directly.
__global__ void gather_kv_kernel(const float* __restrict__ key,
                                 const float* __restrict__ value,
                                 const float* __restrict__ kcache,
                                 const float* __restrict__ vcache,
                                 const int*   __restrict__ bt)
{
    int idx = blockIdx.x * blockDim.x + threadIdx.x;   // float4 index
    if (idx >= BB * NKV * KVL * (HEADD / 4)) return;
    // idx bits: [4:0]=d4, [15:5]=t, [18:16]=h, [20:19]=b ; dst float4 index == idx
    int d4 = idx & 31;
    int t  = (idx >> 5) & (KVL - 1);
    int h  = (idx >> 16) & (NKV - 1);
    int b  = idx >> 19;
    float4 kv, vv;
    if (t < PASTL) {
        int blk  = bt[b * (KVL / 16) + (t >> 4)];
        int slot = blk * 16 + (t & 15);
        size_t off = ((size_t)slot * NKV + h) * 32 + d4;
        kv = ((const float4*)kcache)[off];
        vv = ((const float4*)vcache)[off];
    } else {
        size_t tok = (size_t)b * QL + (t - PASTL);
        size_t off = tok * (NKV * HEADD / 4) + (size_t)h * 32 + d4;
        kv = ((const float4*)key)[off];
        vv = ((const float4*)value)[off];
    }
    ((float4*)g_K)[idx] = kv;
    ((float4*)g_V)[idx] = vv;
}

// Phase 2: flash attention.
// grid.x = b*NKV (32), grid.y = q tile (16 tiles of 32 q positions)
// CTA rows: r = j*32 + qq  (j = grouped query head 0..3, qq = q within tile)
__global__ __launch_bounds__(256, 1)
void attn_kernel(const float* __restrict__ query, float* __restrict__ out)
{
    extern __shared__ float sm[];
    float* Qs = sm + QS_OFF;   // [kk][row] stride QSS
    float* Ks = sm + KS_OFF;   // [kk][c]   stride KSS
    float* Vs = sm + VS_OFF;   // [c][d]    stride 128
    float* Ps = sm + PS_OFF;   // [c][row]  stride PSS
    float* Ms = sm + MS_OFF;
    float* Ls = sm + LS_OFF;
    float* As = sm + AS_OFF;

    const int tid = threadIdx.x;
    const int b   = blockIdx.x >> 3;
    const int h   = blockIdx.x & 7;
    const int q0  = blockIdx.y << 5;

    // log2(e)/sqrt(128): fold softmax scale + base-2 conversion into Q
    const float SCALE = 0.12751740f;

    // ---- load Q tile (128 rows x 128 dims), scaled, transposed to [kk][row]
    for (int idx = tid; idx < MROWS * HEADD; idx += 256) {
        int r  = idx >> 7;           // row
        int kk = idx & 127;          // head dim
        int j  = r >> 5;
        int qq = r & 31;
        float v = query[((size_t)(b * QL + q0 + qq)) * (NQO * HEADD)
                        + (h * GQ + j) * HEADD + kk];
        Qs[kk * QSS + r] = v * SCALE;
    }
    if (tid < MROWS) { Ms[tid] = -1e30f; Ls[tid] = 0.0f; }
    __syncthreads();

    const int ty = tid >> 4;     // 0..15
    const int tx = tid & 15;     // 0..15

    float acc[8][8];
#pragma unroll
    for (int i = 0; i < 8; i++)
#pragma unroll
        for (int j = 0; j < 8; j++) acc[i][j] = 0.0f;

    const int kv_hi  = PASTL + q0 + 31;        // max kv index any row may see
    const int ntiles = kv_hi / NT + 1;

    const float* Kgp = g_K + ((size_t)(b * NKV + h)) * KVL * HEADD;
    const float* Vgp = g_V + ((size_t)(b * NKV + h)) * KVL * HEADD;

    for (int tile = 0; tile < ntiles; ++tile) {
        const int t0 = tile * NT;

        // ---- load K (transposed [kk][c]) and V ([c][d]) tiles
        for (int idx = tid; idx < NT * HEADD; idx += 256) {
            int c  = idx >> 7;
            int kk = idx & 127;
            Ks[kk * KSS + c] = Kgp[(size_t)(t0 + c) * HEADD + kk];
        }
        for (int idx4 = tid; idx4 < NT * (HEADD / 4); idx4 += 256) {
            int c  = idx4 >> 5;
            int d4 = idx4 & 31;
            ((float4*)Vs)[c * 32 + d4] =
                ((const float4*)Vgp)[(size_t)(t0 + c) * 32 + d4];
        }
        __syncthreads();

        // ---- S = Q K^T  (per-thread 8 rows x 4 cols)
        float s[8][4];
#pragma unroll
        for (int i = 0; i < 8; i++)
#pragma unroll
            for (int j = 0; j < 4; j++) s[i][j] = 0.0f;

#pragma unroll 2
        for (int kk = 0; kk < HEADD; ++kk) {
            float qv[8], kvv[4];
#pragma unroll
            for (int i = 0; i < 8; i++) qv[i] = Qs[kk * QSS + ty + 16 * i];
#pragma unroll
            for (int j = 0; j < 4; j++) kvv[j] = Ks[kk * KSS + tx + 16 * j];
#pragma unroll
            for (int i = 0; i < 8; i++)
#pragma unroll
                for (int j = 0; j < 4; j++) s[i][j] = fmaf(qv[i], kvv[j], s[i][j]);
        }

        // ---- causal mask + write S to smem as [c][row]
#pragma unroll
        for (int i = 0; i < 8; i++) {
            int r   = ty + 16 * i;
            int lim = PASTL + q0 + (r & 31);   // max allowed kv index
#pragma unroll
            for (int j = 0; j < 4; j++) {
                int c = tx + 16 * j;
                Ps[c * PSS + r] = ((t0 + c) > lim) ? -1e30f : s[i][j];
            }
        }
        __syncthreads();

        // ---- online softmax, one thread per row
        if (tid < MROWS) {
            int r = tid;
            float mt = -1e30f;
#pragma unroll 4
            for (int c = 0; c < NT; ++c) mt = fmaxf(mt, Ps[c * PSS + r]);
            float mo = Ms[r];
            float mn = fmaxf(mo, mt);
            float al = ex2f(mo - mn);
            float sum = 0.0f;
#pragma unroll 4
            for (int c = 0; c < NT; ++c) {
                float p = ex2f(Ps[c * PSS + r] - mn);
                Ps[c * PSS + r] = p;
                sum += p;
            }
            Ls[r] = Ls[r] * al + sum;
            Ms[r] = mn;
            As[r] = al;
        }
        __syncthreads();

        // ---- rescale O, then O += P V  (per-thread 8x8)
        float al[8];
#pragma unroll
        for (int i = 0; i < 8; i++) al[i] = As[ty + 16 * i];
#pragma unroll
        for (int i = 0; i < 8; i++)
#pragma unroll
            for (int j = 0; j < 8; j++) acc[i][j] *= al[i];

#pragma unroll 2
        for (int c = 0; c < NT; ++c) {
            float pv[8], vv[8];
#pragma unroll
            for (int i = 0; i < 8; i++) pv[i] = Ps[c * PSS + ty + 16 * i];
#pragma unroll
            for (int j = 0; j < 8; j++) vv[j] = Vs[c * HEADD + tx + 16 * j];
#pragma unroll
            for (int i = 0; i < 8; i++)
#pragma unroll
                for (int j = 0; j < 8; j++)
                    acc[i][j] = fmaf(pv[i], vv[j], acc[i][j]);
        }
        __syncthreads();   // before next tile overwrites Ks/Vs/Ps
    }

    // ---- epilogue: divide by l, write out
    float il[8];
#pragma unroll
    for (int i = 0; i < 8; i++) il[i] = 1.0f / Ls[ty + 16 * i];
#pragma unroll
    for (int i = 0; i < 8; i++) {
        int r  = ty + 16 * i;
        int jh = r >> 5;
        int qq = r & 31;
        float* orow = out + ((size_t)(b * QL + q0 + qq)) * (NQO * HEADD)
                          + (h * GQ + jh) * HEADD;
#pragma unroll
        for (int j = 0; j < 8; j++) orow[tx + 16 * j] = acc[i][j] * il[i];
    }
}

extern "C" void kernel_launch(void* const* d_in, const int* in_sizes, int n_in,
                              void* d_out, int out_size)
{
    const float* query  = (const float*)d_in[0];
    const float* key    = (const float*)d_in[1];
    const float* value  = (const float*)d_in[2];
    const float* kcache = (const float*)d_in[3];
    const float* vcache = (const float*)d_in[4];
    const int*   bt     = (const int*)d_in[5];
    // d_in[6] = new_cache_slots (unused: slots are derivable from block_tables)
    float* out = (float*)d_out;

    // Phase 1: gather paged KV into contiguous scratch
    int total4 = BB * NKV * KVL * (HEADD / 4);
    gather_kv_kernel<<<(total4 + 255) / 256, 256>>>(key, value, kcache, vcache, bt);

    // Phase 2: flash attention
    cudaFuncSetAttribute(attn_kernel, cudaFuncAttributeMaxDynamicSharedMemorySize,
                         SMEM_FLOATS * 4);
    dim3 grid(BB * NKV, QL / 32);
    attn_kernel<<<grid, 256, SMEM_FLOATS * 4>>>(query, out);
}